// round 2
// baseline (speedup 1.0000x reference)
#include <cuda_runtime.h>
#include <cstdint>
#include <math.h>

// ============================================================================
// AttentionModel: QKV projection + MHA + jax-threefry dropout, fp32.
//   B=2, S=2048, D=1024, H=16, HD=64
// Round 2 fix: attn_mask arrives as int32 (harness converts bool -> int32);
// previously read as bytes -> garbage masking -> rel_err 1.92.
// ============================================================================

#define JAX_THREEFRY_PARTITIONABLE 1

static constexpr int B_ = 2, H_ = 16, S_ = 2048, D_ = 1024, HD_ = 64;

__device__ float g_q[B_ * S_ * D_];
__device__ float g_k[B_ * S_ * D_];
__device__ float g_v[B_ * S_ * D_];

// ---------------------------------------------------------------------------
// Threefry-2x32 (JAX-compatible), usable at compile time AND on device.
// ---------------------------------------------------------------------------
struct KeyPair { unsigned a, b; };

__host__ __device__ constexpr unsigned rotlc(unsigned x, int r) {
    return (x << r) | (x >> (32 - r));
}

__host__ __device__ constexpr KeyPair threefry_block(unsigned k0, unsigned k1,
                                                     unsigned x0, unsigned x1) {
    unsigned k2 = k0 ^ k1 ^ 0x1BD11BDAu;
    x0 += k0; x1 += k1;
    const int RA[4] = {13, 15, 26, 6};
    const int RB[4] = {17, 29, 16, 24};
    for (int i = 0; i < 4; i++) { x0 += x1; x1 = rotlc(x1, RA[i]); x1 ^= x0; }
    x0 += k1; x1 += k2 + 1u;
    for (int i = 0; i < 4; i++) { x0 += x1; x1 = rotlc(x1, RB[i]); x1 ^= x0; }
    x0 += k2; x1 += k0 + 2u;
    for (int i = 0; i < 4; i++) { x0 += x1; x1 = rotlc(x1, RA[i]); x1 ^= x0; }
    x0 += k0; x1 += k1 + 3u;
    for (int i = 0; i < 4; i++) { x0 += x1; x1 = rotlc(x1, RB[i]); x1 ^= x0; }
    x0 += k1; x1 += k2 + 4u;
    for (int i = 0; i < 4; i++) { x0 += x1; x1 = rotlc(x1, RA[i]); x1 ^= x0; }
    x0 += k2; x1 += k0 + 5u;
    return {x0, x1};
}

// keep = uniform(DROPOUT_KEY, shape)[idx] < 0.9, with
// DROPOUT_KEY = fold_in(key(0), 12345) = threefry((0,0),(0,12345))  [compile-time]
__device__ __forceinline__ bool dropout_keep(unsigned idx) {
    constexpr KeyPair FK = threefry_block(0u, 0u, 0u, 12345u);
#if JAX_THREEFRY_PARTITIONABLE
    // partitionable: bits[i] = y0 ^ y1 of threefry(key, (hi32(i)=0, lo32(i)=i))
    KeyPair r = threefry_block(FK.a, FK.b, 0u, idx);
    unsigned bits = r.a ^ r.b;
#else
    // legacy: iota split into halves; lane0 for i<half, lane1 otherwise
    constexpr unsigned HALF = (unsigned)(B_ * H_) * (unsigned)S_ * (unsigned)(S_ / 2);
    unsigned lo = (idx < HALF) ? idx : idx - HALF;
    KeyPair r = threefry_block(FK.a, FK.b, lo, lo + HALF);
    unsigned bits = (idx < HALF) ? r.a : r.b;
#endif
    float u = __uint_as_float((bits >> 9) | 0x3f800000u) - 1.0f;
    return u < 0.9f;
}

// ---------------------------------------------------------------------------
// Projection GEMM: Y[M=4096, N=1024] = X[4096,1024] @ W[1024,1024]^T + bias
// 64x64 tile, BK=16, 256 threads, 4x4 per thread, pad-17 smem rows.
// ---------------------------------------------------------------------------
__global__ void __launch_bounds__(256) proj_kernel(const float* __restrict__ X,
                                                   const float* __restrict__ W,
                                                   const float* __restrict__ bias,
                                                   float* __restrict__ Y) {
    __shared__ float As[64][17];
    __shared__ float Bs[64][17];
    const int m0 = blockIdx.x << 6;
    const int n0 = blockIdx.y << 6;
    const int t  = threadIdx.x;
    const int tx = t & 15, ty = t >> 4;
    const int lrow = t >> 2, lc4 = (t & 3) << 2;

    float acc[4][4] = {};

    for (int k0 = 0; k0 < D_; k0 += 16) {
        float4 xa = *reinterpret_cast<const float4*>(&X[(size_t)(m0 + lrow) * D_ + k0 + lc4]);
        float4 wb = *reinterpret_cast<const float4*>(&W[(size_t)(n0 + lrow) * D_ + k0 + lc4]);
        __syncthreads();
        As[lrow][lc4 + 0] = xa.x; As[lrow][lc4 + 1] = xa.y;
        As[lrow][lc4 + 2] = xa.z; As[lrow][lc4 + 3] = xa.w;
        Bs[lrow][lc4 + 0] = wb.x; Bs[lrow][lc4 + 1] = wb.y;
        Bs[lrow][lc4 + 2] = wb.z; Bs[lrow][lc4 + 3] = wb.w;
        __syncthreads();
        #pragma unroll
        for (int kk = 0; kk < 16; kk++) {
            float a[4], bb[4];
            #pragma unroll
            for (int i = 0; i < 4; i++) a[i]  = As[4 * ty + i][kk];
            #pragma unroll
            for (int j = 0; j < 4; j++) bb[j] = Bs[4 * tx + j][kk];
            #pragma unroll
            for (int i = 0; i < 4; i++)
                #pragma unroll
                for (int j = 0; j < 4; j++)
                    acc[i][j] += a[i] * bb[j];
        }
    }
    #pragma unroll
    for (int i = 0; i < 4; i++)
        #pragma unroll
        for (int j = 0; j < 4; j++)
            Y[(size_t)(m0 + 4 * ty + i) * D_ + n0 + 4 * tx + j] =
                acc[i][j] + bias[n0 + 4 * tx + j];
}

// ---------------------------------------------------------------------------
// Flash attention: grid (S/64, B*H), 256 threads.
// smem: Qs[64][64] | Ks[64][65] (reused as P) | Vs[64][64]  = 49408 B dynamic
// ---------------------------------------------------------------------------
static constexpr int ATTN_SMEM_BYTES = (64 * 64 + 64 * 65 + 64 * 64) * 4;

__global__ void __launch_bounds__(256) attn_kernel(const int* __restrict__ mask,
                                                   const float* __restrict__ inv_scale_p,
                                                   float* __restrict__ out) {
    extern __shared__ float sm[];
    float* Qs = sm;                      // 64 x 64
    float* Ks = sm + 64 * 64;            // 64 x 65 (later reused as P)
    float* Vs = sm + 64 * 64 + 64 * 65;  // 64 x 64

    const int qt = blockIdx.x;
    const int bh = blockIdx.y;
    const int b  = bh >> 4;
    const int q0 = qt << 6;
    const int t  = threadIdx.x;
    const int tx = t & 15;
    const int ty = t >> 4;
    const int hcol = (bh & 15) << 6;
    const float scale = 1.0f / inv_scale_p[0];

    // ---- load Q tile [64 rows, 64 head-dims] ----
    {
        const int r  = t >> 4;         // 0..15
        const int c4 = (t & 15) << 2;  // 0..60
        #pragma unroll
        for (int p = 0; p < 4; p++) {
            const int rr = r + p * 16;
            float4 v = *reinterpret_cast<const float4*>(
                &g_q[(size_t)(b * S_ + q0 + rr) * D_ + hcol + c4]);
            *reinterpret_cast<float4*>(&Qs[rr * 64 + c4]) = v;
        }
    }

    float m[4], l[4], acc[4][4];
    #pragma unroll
    for (int i = 0; i < 4; i++) {
        m[i] = -INFINITY; l[i] = 0.0f;
        #pragma unroll
        for (int j = 0; j < 4; j++) acc[i][j] = 0.0f;
    }

    unsigned rowbase[4];
    #pragma unroll
    for (int i = 0; i < 4; i++)
        rowbase[i] = ((unsigned)bh * (unsigned)S_ + (unsigned)(q0 + 4 * ty + i)) * (unsigned)S_;

    for (int kt = 0; kt < S_ / 64; kt++) {
        const int kbase = kt << 6;
        __syncthreads();  // previous iter's P/V reads done before overwrite
        {
            const int r  = t >> 4;
            const int c4 = (t & 15) << 2;
            #pragma unroll
            for (int p = 0; p < 4; p++) {
                const int rr = r + p * 16;
                const size_t gof = (size_t)(b * S_ + kbase + rr) * D_ + hcol + c4;
                float4 kv = *reinterpret_cast<const float4*>(&g_k[gof]);
                Ks[rr * 65 + c4 + 0] = kv.x;
                Ks[rr * 65 + c4 + 1] = kv.y;
                Ks[rr * 65 + c4 + 2] = kv.z;
                Ks[rr * 65 + c4 + 3] = kv.w;
                float4 vv = *reinterpret_cast<const float4*>(&g_v[gof]);
                *reinterpret_cast<float4*>(&Vs[rr * 64 + c4]) = vv;
            }
        }
        int mu[4];
        #pragma unroll
        for (int j = 0; j < 4; j++) mu[j] = mask[b * S_ + kbase + 4 * tx + j];
        __syncthreads();

        // ---- S = Q K^T (4x4 per thread) ----
        float s[4][4];
        #pragma unroll
        for (int i = 0; i < 4; i++)
            #pragma unroll
            for (int j = 0; j < 4; j++) s[i][j] = 0.0f;

        #pragma unroll 4
        for (int d4 = 0; d4 < 16; d4++) {
            float4 qa[4];
            #pragma unroll
            for (int i = 0; i < 4; i++)
                qa[i] = *reinterpret_cast<const float4*>(&Qs[(4 * ty + i) * 64 + 4 * d4]);
            #pragma unroll
            for (int j = 0; j < 4; j++) {
                const float* kr = &Ks[(4 * tx + j) * 65 + 4 * d4];
                const float b0 = kr[0], b1 = kr[1], b2 = kr[2], b3 = kr[3];
                #pragma unroll
                for (int i = 0; i < 4; i++)
                    s[i][j] += qa[i].x * b0 + qa[i].y * b1 + qa[i].z * b2 + qa[i].w * b3;
            }
        }

        // ---- mask + online softmax + dropout ----
        float pd[4][4], cf[4];
        #pragma unroll
        for (int i = 0; i < 4; i++) {
            #pragma unroll
            for (int j = 0; j < 4; j++)
                s[i][j] = mu[j] ? s[i][j] * scale : -INFINITY;
            float tm = fmaxf(fmaxf(s[i][0], s[i][1]), fmaxf(s[i][2], s[i][3]));
            #pragma unroll
            for (int o = 1; o < 16; o <<= 1)
                tm = fmaxf(tm, __shfl_xor_sync(0xffffffffu, tm, o));
            const float mn = fmaxf(m[i], tm);
            const float c  = (mn == -INFINITY) ? 1.0f : expf(m[i] - mn);
            float rs = 0.0f;
            #pragma unroll
            for (int j = 0; j < 4; j++) {
                const float p = (mn == -INFINITY) ? 0.0f : expf(s[i][j] - mn);
                rs += p;
                const unsigned idx = rowbase[i] + (unsigned)(kbase + 4 * tx + j);
                pd[i][j] = dropout_keep(idx) ? p * (1.0f / 0.9f) : 0.0f;
            }
            #pragma unroll
            for (int o = 1; o < 16; o <<= 1)
                rs += __shfl_xor_sync(0xffffffffu, rs, o);
            l[i] = l[i] * c + rs;
            m[i] = mn;
            cf[i] = c;
        }
        #pragma unroll
        for (int i = 0; i < 4; i++)
            #pragma unroll
            for (int j = 0; j < 4; j++) acc[i][j] *= cf[i];

        __syncthreads();  // everyone done reading Ks for S
        #pragma unroll
        for (int i = 0; i < 4; i++)
            #pragma unroll
            for (int j = 0; j < 4; j++)
                Ks[(4 * ty + i) * 65 + 4 * tx + j] = pd[i][j];  // Ks reused as P
        __syncthreads();

        // ---- O += P @ V ----
        #pragma unroll 8
        for (int kk = 0; kk < 64; kk++) {
            float4 vj = *reinterpret_cast<const float4*>(&Vs[kk * 64 + 4 * tx]);
            #pragma unroll
            for (int i = 0; i < 4; i++) {
                const float p = Ks[(4 * ty + i) * 65 + kk];
                acc[i][0] += p * vj.x;
                acc[i][1] += p * vj.y;
                acc[i][2] += p * vj.z;
                acc[i][3] += p * vj.w;
            }
        }
    }

    // ---- epilogue: normalize by row sum (undropped) ----
    #pragma unroll
    for (int i = 0; i < 4; i++) {
        const float inv_l = 1.0f / l[i];
        #pragma unroll
        for (int j = 0; j < 4; j++)
            out[((size_t)bh * S_ + q0 + 4 * ty + i) * HD_ + 4 * tx + j] =
                acc[i][j] * inv_l;
    }
}

// ---------------------------------------------------------------------------
extern "C" void kernel_launch(void* const* d_in, const int* in_sizes, int n_in,
                              void* d_out, int out_size) {
    (void)in_sizes; (void)n_in; (void)out_size;
    const float* query = (const float*)d_in[0];
    const float* key   = (const float*)d_in[1];
    const float* value = (const float*)d_in[2];
    const int*   mask  = (const int*)d_in[3];
    const float* invsc = (const float*)d_in[4];
    const float* Wq    = (const float*)d_in[5];
    const float* bq    = (const float*)d_in[6];
    const float* Wk    = (const float*)d_in[7];
    const float* bk    = (const float*)d_in[8];
    const float* Wv    = (const float*)d_in[9];
    const float* bv    = (const float*)d_in[10];
    float*       out   = (float*)d_out;

    float *qp, *kp, *vp;
    cudaGetSymbolAddress((void**)&qp, g_q);
    cudaGetSymbolAddress((void**)&kp, g_k);
    cudaGetSymbolAddress((void**)&vp, g_v);

    dim3 pg(B_ * S_ / 64, D_ / 64);
    proj_kernel<<<pg, 256>>>(query, Wq, bq, qp);
    proj_kernel<<<pg, 256>>>(key,   Wk, bk, kp);
    proj_kernel<<<pg, 256>>>(value, Wv, bv, vp);

    cudaFuncSetAttribute(attn_kernel, cudaFuncAttributeMaxDynamicSharedMemorySize,
                         ATTN_SMEM_BYTES);
    dim3 ag(S_ / 64, B_ * H_);
    attn_kernel<<<ag, 256, ATTN_SMEM_BYTES>>>(mask, invsc, out);
}

// round 5
// speedup vs baseline: 2.1330x; 2.1330x over previous
#include <cuda_runtime.h>
#include <cstdint>
#include <math.h>

// ============================================================================
// AttentionModel: QKV projection + MHA + jax-threefry dropout.
//   B=2, S=2048, D=1024, H=16, HD=64
// Round 5 (3rd attempt at tf32-MMA; prior two runs died to container infra):
//   proj_mma_kernel x3 : 128x64 block tile, 8 warps, tf32 m16n8k8
//   attn_mma_kernel    : 128 q-rows/block, 8 warps, warp m16 x n64,
//                        XOR-swizzled smem (bases hoisted), P smem roundtrip,
//                        online softmax + exact JAX threefry dropout.
// ============================================================================

static constexpr int B_ = 2, H_ = 16, S_ = 2048, D_ = 1024, HD_ = 64;

__device__ float g_q[B_ * S_ * D_];
__device__ float g_k[B_ * S_ * D_];
__device__ float g_v[B_ * S_ * D_];

// ---------------------------------------------------------------------------
// tf32 helpers
// ---------------------------------------------------------------------------
__device__ __forceinline__ float f2tf32f(float x) {
    uint32_t r;
    asm("cvt.rna.tf32.f32 %0, %1;" : "=r"(r) : "f"(x));
    return __uint_as_float(r);
}

__device__ __forceinline__ void mma_tf32(float c[4],
                                         uint32_t a0, uint32_t a1, uint32_t a2, uint32_t a3,
                                         uint32_t b0, uint32_t b1) {
    asm volatile(
        "mma.sync.aligned.m16n8k8.row.col.f32.tf32.tf32.f32 "
        "{%0,%1,%2,%3}, {%4,%5,%6,%7}, {%8,%9}, {%0,%1,%2,%3};"
        : "+f"(c[0]), "+f"(c[1]), "+f"(c[2]), "+f"(c[3])
        : "r"(a0), "r"(a1), "r"(a2), "r"(a3), "r"(b0), "r"(b1));
}

// ---------------------------------------------------------------------------
// Threefry-2x32 (JAX partitionable scheme) — verified exact in Round 2.
// ---------------------------------------------------------------------------
struct KeyPair { unsigned a, b; };

__host__ __device__ constexpr unsigned rotlc(unsigned x, int r) {
    return (x << r) | (x >> (32 - r));
}

__host__ __device__ constexpr KeyPair threefry_block(unsigned k0, unsigned k1,
                                                     unsigned x0, unsigned x1) {
    unsigned k2 = k0 ^ k1 ^ 0x1BD11BDAu;
    x0 += k0; x1 += k1;
    const int RA[4] = {13, 15, 26, 6};
    const int RB[4] = {17, 29, 16, 24};
    for (int i = 0; i < 4; i++) { x0 += x1; x1 = rotlc(x1, RA[i]); x1 ^= x0; }
    x0 += k1; x1 += k2 + 1u;
    for (int i = 0; i < 4; i++) { x0 += x1; x1 = rotlc(x1, RB[i]); x1 ^= x0; }
    x0 += k2; x1 += k0 + 2u;
    for (int i = 0; i < 4; i++) { x0 += x1; x1 = rotlc(x1, RA[i]); x1 ^= x0; }
    x0 += k0; x1 += k1 + 3u;
    for (int i = 0; i < 4; i++) { x0 += x1; x1 = rotlc(x1, RB[i]); x1 ^= x0; }
    x0 += k1; x1 += k2 + 4u;
    for (int i = 0; i < 4; i++) { x0 += x1; x1 = rotlc(x1, RA[i]); x1 ^= x0; }
    x0 += k2; x1 += k0 + 5u;
    return {x0, x1};
}

__device__ __forceinline__ bool dropout_keep(unsigned idx) {
    constexpr KeyPair FK = threefry_block(0u, 0u, 0u, 12345u);
    KeyPair r = threefry_block(FK.a, FK.b, 0u, idx);
    unsigned bits = r.a ^ r.b;
    float u = __uint_as_float((bits >> 9) | 0x3f800000u) - 1.0f;
    return u < 0.9f;
}

// ---------------------------------------------------------------------------
// Projection GEMM (tf32 mma): Y[4096,1024] = X @ W^T + bias
// ---------------------------------------------------------------------------
__global__ void __launch_bounds__(256) proj_mma_kernel(const float* __restrict__ X,
                                                       const float* __restrict__ W,
                                                       const float* __restrict__ bias,
                                                       float* __restrict__ Y) {
    __shared__ float Xs[128 * 36];
    __shared__ float Ws[64 * 36];

    const int m0 = blockIdx.x << 7;
    const int n0 = blockIdx.y << 6;
    const int t  = threadIdx.x;
    const int lane = t & 31, w = t >> 5;
    const int grp = lane >> 2, qd = lane & 3;
    const int wm = w >> 1, wn = w & 1;

    const int frow = t >> 3;          // 0..31
    const int fc4  = (t & 7) << 2;    // 0..28

    float acc[2][4][4];
    #pragma unroll
    for (int mt = 0; mt < 2; mt++)
        #pragma unroll
        for (int nt = 0; nt < 4; nt++)
            #pragma unroll
            for (int r = 0; r < 4; r++) acc[mt][nt][r] = 0.0f;

    // hoisted fragment base pointers
    const float* xa0 = &Xs[(wm * 32 + grp) * 36 + qd];
    const float* xa1 = &Xs[(wm * 32 + 16 + grp) * 36 + qd];
    const float* wb  = &Ws[(wn * 32 + grp) * 36 + qd];

    for (int k0 = 0; k0 < D_; k0 += 32) {
        __syncthreads();
        #pragma unroll
        for (int l = 0; l < 4; l++) {
            const int row = frow + (l << 5);
            float4 v = *reinterpret_cast<const float4*>(&X[(size_t)(m0 + row) * D_ + k0 + fc4]);
            float* d = &Xs[row * 36 + fc4];
            d[0] = f2tf32f(v.x); d[1] = f2tf32f(v.y); d[2] = f2tf32f(v.z); d[3] = f2tf32f(v.w);
        }
        #pragma unroll
        for (int l = 0; l < 2; l++) {
            const int row = frow + (l << 5);
            float4 v = *reinterpret_cast<const float4*>(&W[(size_t)(n0 + row) * D_ + k0 + fc4]);
            float* d = &Ws[row * 36 + fc4];
            d[0] = f2tf32f(v.x); d[1] = f2tf32f(v.y); d[2] = f2tf32f(v.z); d[3] = f2tf32f(v.w);
        }
        __syncthreads();

        #pragma unroll
        for (int k8 = 0; k8 < 4; k8++) {
            const int kk = k8 << 3;
            uint32_t a[2][4];
            #pragma unroll
            for (int mt = 0; mt < 2; mt++) {
                const float* base = mt ? xa1 : xa0;
                a[mt][0] = __float_as_uint(base[kk]);
                a[mt][1] = __float_as_uint(base[8 * 36 + kk]);
                a[mt][2] = __float_as_uint(base[kk + 4]);
                a[mt][3] = __float_as_uint(base[8 * 36 + kk + 4]);
            }
            #pragma unroll
            for (int nt = 0; nt < 4; nt++) {
                uint32_t b0 = __float_as_uint(wb[nt * 8 * 36 + kk]);
                uint32_t b1 = __float_as_uint(wb[nt * 8 * 36 + kk + 4]);
                mma_tf32(acc[0][nt], a[0][0], a[0][1], a[0][2], a[0][3], b0, b1);
                mma_tf32(acc[1][nt], a[1][0], a[1][1], a[1][2], a[1][3], b0, b1);
            }
        }
    }

    #pragma unroll
    for (int mt = 0; mt < 2; mt++) {
        const int r0 = m0 + wm * 32 + mt * 16 + grp;
        #pragma unroll
        for (int nt = 0; nt < 4; nt++) {
            const int c = n0 + wn * 32 + nt * 8 + (qd << 1);
            const float b0 = bias[c], b1 = bias[c + 1];
            float2 v0 = make_float2(acc[mt][nt][0] + b0, acc[mt][nt][1] + b1);
            float2 v1 = make_float2(acc[mt][nt][2] + b0, acc[mt][nt][3] + b1);
            *reinterpret_cast<float2*>(&Y[(size_t)r0 * D_ + c]) = v0;
            *reinterpret_cast<float2*>(&Y[(size_t)(r0 + 8) * D_ + c]) = v1;
        }
    }
}

// ---------------------------------------------------------------------------
// Flash attention (tf32 mma): grid (S/128, B*H), 256 thr (8 warps).
// smem: Qs[128][72] swz | Ks[64][72] swz | Vs[64][72] plain | Ps[128][72] swz
// ---------------------------------------------------------------------------
static constexpr int ATTN_SMEM_FLOATS = 128 * 72 + 64 * 72 + 64 * 72 + 128 * 72 + 64;
static constexpr int ATTN_SMEM_BYTES  = ATTN_SMEM_FLOATS * 4;

__global__ void __launch_bounds__(256) attn_mma_kernel(const int* __restrict__ mask,
                                                       const float* __restrict__ inv_scale_p,
                                                       float* __restrict__ out) {
    extern __shared__ float sm[];
    float* Qs = sm;                       // 128 x 72, xor-swizzled quads
    float* Ks = Qs + 128 * 72;            // 64 x 72, xor-swizzled
    float* Vs = Ks + 64 * 72;             // 64 x 72, plain
    float* Ps = Vs + 64 * 72;             // 128 x 72, xor-swizzled
    int*   Ms = (int*)(Ps + 128 * 72);    // 64

    const int q0 = blockIdx.x << 7;
    const int bh = blockIdx.y;
    const int b  = bh >> 4;
    const int hcol = (bh & 15) << 6;
    const int t = threadIdx.x;
    const int lane = t & 31, w = t >> 5;
    const int grp = lane >> 2, qd = lane & 3;
    const int R0 = (w << 4) + grp;        // local q row; R1 = R0 + 8
    const int sw0 = R0 & 15, sw1 = (R0 + 8) & 15;  // row swizzle keys
    const float scale = 1.0f / inv_scale_p[0];

    // hoisted row bases
    float* Q0 = &Qs[R0 * 72];
    float* Q1 = &Qs[(R0 + 8) * 72];
    float* P0 = &Ps[R0 * 72];
    float* P1 = &Ps[(R0 + 8) * 72];

    // ---- load Q tile (swizzled, tf32) ----
    {
        const int cq = t & 15;
        #pragma unroll
        for (int l = 0; l < 8; l++) {
            const int row = (t >> 4) + (l << 4);
            float4 v = *reinterpret_cast<const float4*>(
                &g_q[(size_t)(b * S_ + q0 + row) * D_ + hcol + (cq << 2)]);
            float* d = &Qs[row * 72 + ((cq ^ (row & 15)) << 2)];
            d[0] = f2tf32f(v.x); d[1] = f2tf32f(v.y); d[2] = f2tf32f(v.z); d[3] = f2tf32f(v.w);
        }
    }

    float oacc[8][4];
    #pragma unroll
    for (int nt = 0; nt < 8; nt++)
        #pragma unroll
        for (int r = 0; r < 4; r++) oacc[nt][r] = 0.0f;
    float mrow0 = -INFINITY, mrow1 = -INFINITY;
    float lrow0 = 0.0f, lrow1 = 0.0f;

    const unsigned rb0 = ((unsigned)bh * S_ + (unsigned)(q0 + R0)) * (unsigned)S_;
    const unsigned rb1 = rb0 + 8u * S_;

    for (int kt = 0; kt < S_ / 64; kt++) {
        const int kbase = kt << 6;
        __syncthreads();
        // ---- K/V tile fill ----
        {
            const int cq = t & 15;
            #pragma unroll
            for (int l = 0; l < 4; l++) {
                const int row = (t >> 4) + (l << 4);
                const size_t gof = (size_t)(b * S_ + kbase + row) * D_ + hcol + (cq << 2);
                float4 kv = *reinterpret_cast<const float4*>(&g_k[gof]);
                float* dk = &Ks[row * 72 + ((cq ^ (row & 15)) << 2)];
                dk[0] = f2tf32f(kv.x); dk[1] = f2tf32f(kv.y);
                dk[2] = f2tf32f(kv.z); dk[3] = f2tf32f(kv.w);
                float4 vv = *reinterpret_cast<const float4*>(&g_v[gof]);
                float* dv = &Vs[row * 72 + (cq << 2)];
                dv[0] = f2tf32f(vv.x); dv[1] = f2tf32f(vv.y);
                dv[2] = f2tf32f(vv.z); dv[3] = f2tf32f(vv.w);
            }
            if (t < 64) Ms[t] = mask[b * S_ + kbase + t];
        }
        __syncthreads();

        // ---- S = Q K^T ----
        float sacc[8][4];
        #pragma unroll
        for (int nt = 0; nt < 8; nt++)
            #pragma unroll
            for (int r = 0; r < 4; r++) sacc[nt][r] = 0.0f;

        #pragma unroll
        for (int k8 = 0; k8 < 8; k8++) {
            const int cqa = 2 * k8;
            uint32_t a0 = __float_as_uint(Q0[((cqa ^ sw0) << 2) + qd]);
            uint32_t a1 = __float_as_uint(Q1[((cqa ^ sw1) << 2) + qd]);
            uint32_t a2 = __float_as_uint(Q0[(((cqa + 1) ^ sw0) << 2) + qd]);
            uint32_t a3 = __float_as_uint(Q1[(((cqa + 1) ^ sw1) << 2) + qd]);
            #pragma unroll
            for (int nt = 0; nt < 8; nt++) {
                const int key = (nt << 3) + grp;
                const int ksw = key & 15;
                const float* kr = &Ks[key * 72];
                uint32_t b0 = __float_as_uint(kr[((cqa ^ ksw) << 2) + qd]);
                uint32_t b1 = __float_as_uint(kr[(((cqa + 1) ^ ksw) << 2) + qd]);
                mma_tf32(sacc[nt], a0, a1, a2, a3, b0, b1);
            }
        }

        // ---- mask + scale ----
        #pragma unroll
        for (int nt = 0; nt < 8; nt++) {
            const int col = (nt << 3) + (qd << 1);
            const int mu0 = Ms[col], mu1 = Ms[col + 1];
            sacc[nt][0] = mu0 ? sacc[nt][0] * scale : -INFINITY;
            sacc[nt][1] = mu1 ? sacc[nt][1] * scale : -INFINITY;
            sacc[nt][2] = mu0 ? sacc[nt][2] * scale : -INFINITY;
            sacc[nt][3] = mu1 ? sacc[nt][3] * scale : -INFINITY;
        }

        // ---- row max (quad shuffle) ----
        float mx0 = -INFINITY, mx1 = -INFINITY;
        #pragma unroll
        for (int nt = 0; nt < 8; nt++) {
            mx0 = fmaxf(mx0, fmaxf(sacc[nt][0], sacc[nt][1]));
            mx1 = fmaxf(mx1, fmaxf(sacc[nt][2], sacc[nt][3]));
        }
        #pragma unroll
        for (int o = 1; o < 4; o <<= 1) {
            mx0 = fmaxf(mx0, __shfl_xor_sync(0xffffffffu, mx0, o));
            mx1 = fmaxf(mx1, __shfl_xor_sync(0xffffffffu, mx1, o));
        }
        const float mn0 = fmaxf(mrow0, mx0);
        const float mn1 = fmaxf(mrow1, mx1);
        const float me0 = (mn0 == -INFINITY) ? 0.0f : mn0;
        const float me1 = (mn1 == -INFINITY) ? 0.0f : mn1;
        const float cf0 = (mrow0 == -INFINITY) ? ((mn0 == -INFINITY) ? 1.0f : 0.0f)
                                               : __expf(mrow0 - me0);
        const float cf1 = (mrow1 == -INFINITY) ? ((mn1 == -INFINITY) ? 1.0f : 0.0f)
                                               : __expf(mrow1 - me1);

        // ---- exp, dropout, P store ----
        float rs0 = 0.0f, rs1 = 0.0f;
        #pragma unroll
        for (int nt = 0; nt < 8; nt++) {
            const int col = (nt << 3) + (qd << 1);
            const unsigned gcol = (unsigned)(kbase + col);
            const float p00 = __expf(sacc[nt][0] - me0);
            const float p01 = __expf(sacc[nt][1] - me0);
            const float p10 = __expf(sacc[nt][2] - me1);
            const float p11 = __expf(sacc[nt][3] - me1);
            rs0 += p00 + p01;
            rs1 += p10 + p11;
            const float d00 = dropout_keep(rb0 + gcol)      ? p00 * (1.0f / 0.9f) : 0.0f;
            const float d01 = dropout_keep(rb0 + gcol + 1u) ? p01 * (1.0f / 0.9f) : 0.0f;
            const float d10 = dropout_keep(rb1 + gcol)      ? p10 * (1.0f / 0.9f) : 0.0f;
            const float d11 = dropout_keep(rb1 + gcol + 1u) ? p11 * (1.0f / 0.9f) : 0.0f;
            const int pcq = (nt << 1) + (qd >> 1);
            const int lo  = (qd & 1) << 1;
            *reinterpret_cast<float2*>(&P0[((pcq ^ sw0) << 2) + lo]) =
                make_float2(f2tf32f(d00), f2tf32f(d01));
            *reinterpret_cast<float2*>(&P1[((pcq ^ sw1) << 2) + lo]) =
                make_float2(f2tf32f(d10), f2tf32f(d11));
        }
        #pragma unroll
        for (int o = 1; o < 4; o <<= 1) {
            rs0 += __shfl_xor_sync(0xffffffffu, rs0, o);
            rs1 += __shfl_xor_sync(0xffffffffu, rs1, o);
        }
        lrow0 = lrow0 * cf0 + rs0;
        lrow1 = lrow1 * cf1 + rs1;
        mrow0 = mn0;
        mrow1 = mn1;
        #pragma unroll
        for (int nt = 0; nt < 8; nt++) {
            oacc[nt][0] *= cf0; oacc[nt][1] *= cf0;
            oacc[nt][2] *= cf1; oacc[nt][3] *= cf1;
        }
        __syncwarp();

        // ---- O += P V ----
        #pragma unroll
        for (int k8 = 0; k8 < 8; k8++) {
            const int cqa = 2 * k8;
            uint32_t a0 = __float_as_uint(P0[((cqa ^ sw0) << 2) + qd]);
            uint32_t a1 = __float_as_uint(P1[((cqa ^ sw1) << 2) + qd]);
            uint32_t a2 = __float_as_uint(P0[(((cqa + 1) ^ sw0) << 2) + qd]);
            uint32_t a3 = __float_as_uint(P1[(((cqa + 1) ^ sw1) << 2) + qd]);
            const float* v0 = &Vs[((k8 << 3) + qd) * 72 + grp];
            #pragma unroll
            for (int nt = 0; nt < 8; nt++) {
                uint32_t b0 = __float_as_uint(v0[nt << 3]);
                uint32_t b1 = __float_as_uint(v0[4 * 72 + (nt << 3)]);
                mma_tf32(oacc[nt], a0, a1, a2, a3, b0, b1);
            }
        }
    }

    // ---- epilogue ----
    const float il0 = 1.0f / lrow0;
    const float il1 = 1.0f / lrow1;
    const size_t g0 = ((size_t)bh * S_ + q0 + R0) * HD_;
    const size_t g1 = ((size_t)bh * S_ + q0 + R0 + 8) * HD_;
    #pragma unroll
    for (int nt = 0; nt < 8; nt++) {
        const int col = (nt << 3) + (qd << 1);
        *reinterpret_cast<float2*>(&out[g0 + col]) =
            make_float2(oacc[nt][0] * il0, oacc[nt][1] * il0);
        *reinterpret_cast<float2*>(&out[g1 + col]) =
            make_float2(oacc[nt][2] * il1, oacc[nt][3] * il1);
    }
}

// ---------------------------------------------------------------------------
extern "C" void kernel_launch(void* const* d_in, const int* in_sizes, int n_in,
                              void* d_out, int out_size) {
    (void)in_sizes; (void)n_in; (void)out_size;
    const float* query = (const float*)d_in[0];
    const float* key   = (const float*)d_in[1];
    const float* value = (const float*)d_in[2];
    const int*   mask  = (const int*)d_in[3];
    const float* invsc = (const float*)d_in[4];
    const float* Wq    = (const float*)d_in[5];
    const float* bq    = (const float*)d_in[6];
    const float* Wk    = (const float*)d_in[7];
    const float* bk    = (const float*)d_in[8];
    const float* Wv    = (const float*)d_in[9];
    const float* bv    = (const float*)d_in[10];
    float*       out   = (float*)d_out;

    float *qp, *kp, *vp;
    cudaGetSymbolAddress((void**)&qp, g_q);
    cudaGetSymbolAddress((void**)&kp, g_k);
    cudaGetSymbolAddress((void**)&vp, g_v);

    dim3 pg(B_ * S_ / 128, D_ / 64);
    proj_mma_kernel<<<pg, 256>>>(query, Wq, bq, qp);
    proj_mma_kernel<<<pg, 256>>>(key,   Wk, bk, kp);
    proj_mma_kernel<<<pg, 256>>>(value, Wv, bv, vp);

    cudaFuncSetAttribute(attn_mma_kernel, cudaFuncAttributeMaxDynamicSharedMemorySize,
                         ATTN_SMEM_BYTES);
    dim3 ag(S_ / 128, B_ * H_);
    attn_mma_kernel<<<ag, 256, ATTN_SMEM_BYTES>>>(mask, invsc, out);
}